// round 10
// baseline (speedup 1.0000x reference)
#include <cuda_runtime.h>
#include <cuda_bf16.h>
#include <math.h>
#include <stdint.h>

#define BB 4096
#define SS 64
#define HH 128
#define NROWS (BB*SS)

// ---------------------------------------------------------------------------
// Device scratch
// ---------------------------------------------------------------------------
__device__ float g_state1[NROWS*HH];
__device__ float g_state3[NROWS*HH];
__device__ float g_rowsum[BB*HH];
__device__ __align__(16) __nv_bfloat16 g_W1img[SS*2*16384];   // [s][hi/lo][o=128][k=128]
__device__ __align__(16) __nv_bfloat16 g_W3img[SS*2*16384];
__device__ __align__(16) __nv_bfloat16 g_Wihimg[2*2*24576];   // [kchunk][hi/lo][n=384][k=64]
__device__ __align__(16) __nv_bfloat16 g_Whhimg[2*2*24576];

__device__ __forceinline__ uint32_t smem_u32(const void* p) {
  uint32_t a;
  asm("{ .reg .u64 t; cvta.to.shared.u64 t, %1; cvt.u32.u64 %0, t; }" : "=r"(a) : "l"(p));
  return a;
}
__device__ __forceinline__ void ldsm4(uint32_t* r, uint32_t addr) {
  asm volatile("ldmatrix.sync.aligned.m8n8.x4.shared.b16 {%0,%1,%2,%3}, [%4];"
               : "=r"(r[0]), "=r"(r[1]), "=r"(r[2]), "=r"(r[3]) : "r"(addr));
}
__device__ __forceinline__ void mma16816(float* d, const uint32_t* a, const uint32_t* b) {
  asm volatile(
    "mma.sync.aligned.m16n8k16.row.col.f32.bf16.bf16.f32 "
    "{%0,%1,%2,%3}, {%4,%5,%6,%7}, {%8,%9}, {%0,%1,%2,%3};"
    : "+f"(d[0]), "+f"(d[1]), "+f"(d[2]), "+f"(d[3])
    : "r"(a[0]), "r"(a[1]), "r"(a[2]), "r"(a[3]), "r"(b[0]), "r"(b[1]));
}
__device__ __forceinline__ void split8(const float* v, uint4& hiq, uint4& loq) {
  __nv_bfloat16 hv[8], lv[8];
  #pragma unroll
  for (int j = 0; j < 8; j++) {
    hv[j] = __float2bfloat16(v[j]);
    lv[j] = __float2bfloat16(v[j] - __bfloat162float(hv[j]));
  }
  hiq = *(uint4*)hv; loq = *(uint4*)lv;
}
__device__ __forceinline__ void cpasync16(uint32_t dst, const void* src) {
  asm volatile("cp.async.cg.shared.global [%0], [%1], 16;" :: "r"(dst), "l"(src));
}
#define CP_COMMIT() asm volatile("cp.async.commit_group;" ::: "memory")
#define CP_WAIT(n)  asm volatile("cp.async.wait_group %0;" :: "n"(n) : "memory")

// ---------------------------------------------------------------------------
// Prep: split weights into bf16 hi/lo
// ---------------------------------------------------------------------------
__global__ void prep_kernel(const float* __restrict__ W1, const float* __restrict__ W3,
                            const float* __restrict__ Wih, const float* __restrict__ Whh) {
  const int total1 = SS * 128 * 128;
  for (int idx = blockIdx.x * blockDim.x + threadIdx.x; idx < total1;
       idx += gridDim.x * blockDim.x) {
    int s = idx >> 14, r = idx & 16383;
    float w = W1[idx];
    __nv_bfloat16 h = __float2bfloat16(w);
    g_W1img[s*32768 + r]         = h;
    g_W1img[s*32768 + 16384 + r] = __float2bfloat16(w - __bfloat162float(h));
    w = W3[idx];
    h = __float2bfloat16(w);
    g_W3img[s*32768 + r]         = h;
    g_W3img[s*32768 + 16384 + r] = __float2bfloat16(w - __bfloat162float(h));
  }
  const int total2 = 384 * 128;
  for (int idx = blockIdx.x * blockDim.x + threadIdx.x; idx < total2;
       idx += gridDim.x * blockDim.x) {
    int j = idx >> 7, k = idx & 127;
    int c = k >> 6, kc = k & 63;
    int o = j*64 + kc;
    float w = Wih[idx];
    __nv_bfloat16 h = __float2bfloat16(w);
    g_Wihimg[c*49152 + o]         = h;
    g_Wihimg[c*49152 + 24576 + o] = __float2bfloat16(w - __bfloat162float(h));
    w = Whh[idx];
    h = __float2bfloat16(w);
    g_Whhimg[c*49152 + o]         = h;
    g_Whhimg[c*49152 + 24576 + o] = __float2bfloat16(w - __bfloat162float(h));
  }
}

// ---------------------------------------------------------------------------
// K1/K3: per-s GEMM via mma.sync (B via cp.async overlapped with A split)
// ---------------------------------------------------------------------------
#define GP 272
#define G_AHI 0
#define G_ALO (128*GP)
#define G_BHI (2*128*GP)
#define G_BLO (3*128*GP)
#define G_SMEM (4*128*GP)

__global__ __launch_bounds__(256, 1)
void gemm_s_mma(const float* __restrict__ in, const float* __restrict__ rowsum,
                const __nv_bfloat16* __restrict__ Wimg, const float* __restrict__ bias,
                float* __restrict__ out) {
  extern __shared__ char smem[];
  const uint32_t sb = smem_u32(smem);
  const int s = blockIdx.y, b0 = blockIdx.x * 128, t = threadIdx.x;
  const int wid = t >> 5, lane = t & 31;

  // ---- B via cp.async (overlaps with A work below) ----
  {
    const __nv_bfloat16* whi = Wimg + (size_t)s * 32768;
    #pragma unroll
    for (int i = 0; i < 8; i++) {
      int ci = i*256 + t;
      int row = ci >> 4, kq = ci & 15;
      cpasync16(sb + G_BHI + row*GP + kq*16, whi + row*128 + kq*8);
      cpasync16(sb + G_BLO + row*GP + kq*16, whi + 16384 + row*128 + kq*8);
    }
    CP_COMMIT();
  }
  // ---- A load (fp32), split hi/lo ----
  #pragma unroll
  for (int i = 0; i < 8; i++) {
    int ci = i*256 + t;
    int row = ci >> 4, kq = ci & 15, k0 = kq*8;
    const float* src = in + (size_t)(b0 + row)*SS*HH + s*HH + k0;
    float v[8];
    float4 a0 = *(const float4*)src, a1 = *(const float4*)(src + 4);
    v[0]=a0.x; v[1]=a0.y; v[2]=a0.z; v[3]=a0.w; v[4]=a1.x; v[5]=a1.y; v[6]=a1.z; v[7]=a1.w;
    if (rowsum) {
      const float* rp = rowsum + (size_t)(b0 + row)*HH + k0;
      float4 r0 = __ldg((const float4*)rp), r1 = __ldg((const float4*)(rp + 4));
      v[0]=r0.x-v[0]; v[1]=r0.y-v[1]; v[2]=r0.z-v[2]; v[3]=r0.w-v[3];
      v[4]=r1.x-v[4]; v[5]=r1.y-v[5]; v[6]=r1.z-v[6]; v[7]=r1.w-v[7];
    }
    uint4 hq, lq;
    split8(v, hq, lq);
    *(uint4*)(smem + G_AHI + row*GP + kq*16) = hq;
    *(uint4*)(smem + G_ALO + row*GP + kq*16) = lq;
  }
  CP_WAIT(0);
  __syncthreads();

  // ---- MMA mainloop ----
  const int wm = wid >> 1, wn = wid & 1;
  const int m0 = wm*32, n0 = wn*64;
  float acc[2][8][4];
  #pragma unroll
  for (int i = 0; i < 2; i++)
    #pragma unroll
    for (int j = 0; j < 8; j++)
      #pragma unroll
      for (int e = 0; e < 4; e++) acc[i][j][e] = 0.f;

  const uint32_t aoffs[3] = {G_AHI, G_ALO, G_AHI};
  const uint32_t boffs[3] = {G_BHI, G_BHI, G_BLO};
  const uint32_t a_lane = (uint32_t)((m0 + (lane & 15))*GP + (lane >> 4)*16);
  const uint32_t b_lane = (uint32_t)((n0 + ((lane >> 4) << 3) + (lane & 7))*GP + ((lane >> 3) & 1)*16);

  #pragma unroll
  for (int pass = 0; pass < 3; pass++) {
    uint32_t ab = sb + aoffs[pass] + a_lane;
    uint32_t bb = sb + boffs[pass] + b_lane;
    #pragma unroll
    for (int ks = 0; ks < 8; ks++) {
      uint32_t a0[4], a1[4];
      ldsm4(a0, ab + ks*32);
      ldsm4(a1, ab + 16*GP + ks*32);
      #pragma unroll
      for (int np = 0; np < 4; np++) {
        uint32_t b4[4];
        ldsm4(b4, bb + np*16*GP + ks*32);
        mma16816(acc[0][np*2],   a0, b4);
        mma16816(acc[0][np*2+1], a0, b4+2);
        mma16816(acc[1][np*2],   a1, b4);
        mma16816(acc[1][np*2+1], a1, b4+2);
      }
    }
  }

  // ---- epilogue ----
  const int r_lo = lane >> 2, c_off = (lane & 3)*2;
  #pragma unroll
  for (int mt = 0; mt < 2; mt++) {
    #pragma unroll
    for (int nt = 0; nt < 8; nt++) {
      int col = n0 + nt*8 + c_off;
      float bv0 = __ldg(bias + s*HH + col);
      float bv1 = __ldg(bias + s*HH + col + 1);
      int row = b0 + m0 + mt*16 + r_lo;
      float* op = out + (size_t)row*SS*HH + s*HH + col;
      *(float2*)op = make_float2(acc[mt][nt][0] + bv0, acc[mt][nt][1] + bv1);
      op += (size_t)8*SS*HH;
      *(float2*)op = make_float2(acc[mt][nt][2] + bv0, acc[mt][nt][3] + bv1);
    }
  }
}

// ---------------------------------------------------------------------------
// K2: rowsum
// ---------------------------------------------------------------------------
__global__ void rowsum_kernel(const float* __restrict__ st1, float* __restrict__ rs) {
  int idx = blockIdx.x*blockDim.x + threadIdx.x;
  int b = idx >> 5, h4 = (idx & 31)*4;
  const float* p = st1 + (size_t)b*SS*HH + h4;
  float4 a = make_float4(0.f,0.f,0.f,0.f);
  #pragma unroll 8
  for (int s = 0; s < SS; s++) {
    float4 v = __ldg((const float4*)(p + (size_t)s*HH));
    a.x += v.x; a.y += v.y; a.z += v.z; a.w += v.w;
  }
  *(float4*)(rs + (size_t)b*HH + h4) = a;
}

// ---------------------------------------------------------------------------
// K4: fused GRU, balanced warps + cp.async pipelined B.
// 8 warps = 2 rowgroups x 4 "g" warps. Warp g handles:
//   dense RZ cols [g*64, g*64+64)  (both phases, K=128 each)
//   gi cols [g*32, g*32+32) in phase 0;  gh cols [g*32..) in phase 1
// B buffers: Bh x2 (double-buffered), Bl x1.
// Chunk q = phase*2 + kchunk; passes: (Ah,Bh),(Al,Bh),(Ah,Bl).
// ---------------------------------------------------------------------------
#define RBP 144
#define R_AHI 0
#define R_ALO 17408
#define R_BH0 34816
#define R_BH1 90112
#define R_BL  145408
#define R_STAG 34816
#define R_SMEM 200704

__device__ __forceinline__ void gru_loadA(const float* __restrict__ src, int row0,
                                          char* smem, int t) {
  #pragma unroll
  for (int i = 0; i < 4; i++) {
    int ci = i*256 + t;
    int row = ci >> 4, kq = ci & 15;
    const float* sp = src + (size_t)(row0 + row)*HH + kq*8;
    float v[8];
    float4 x0 = *(const float4*)sp, x1 = *(const float4*)(sp + 4);
    v[0]=x0.x; v[1]=x0.y; v[2]=x0.z; v[3]=x0.w; v[4]=x1.x; v[5]=x1.y; v[6]=x1.z; v[7]=x1.w;
    uint4 hq, lq;
    split8(v, hq, lq);
    *(uint4*)(smem + R_AHI + row*GP + kq*16) = hq;
    *(uint4*)(smem + R_ALO + row*GP + kq*16) = lq;
  }
}
// issue one 384x64 bf16 image (hi or lo) into padded smem via cp.async
__device__ __forceinline__ void gru_issueB(const __nv_bfloat16* __restrict__ src,
                                           uint32_t sb, uint32_t dstBase, int t) {
  #pragma unroll
  for (int i = 0; i < 12; i++) {
    int ci = i*256 + t;
    int row = ci >> 3, kq = ci & 7;
    cpasync16(sb + dstBase + row*RBP + kq*16, src + row*64 + kq*8);
  }
  CP_COMMIT();
}

__global__ __launch_bounds__(256, 1)
void gru_mma(const float* __restrict__ feat, const float* __restrict__ st3,
             const float* __restrict__ b_ih, const float* __restrict__ b_hh,
             float* __restrict__ out) {
  extern __shared__ char smem[];
  const uint32_t sb = smem_u32(smem);
  const int row0 = blockIdx.x * 64, t = threadIdx.x;
  const int wid = t >> 5, lane = t & 31;
  const int wm = wid >> 2, g = wid & 3;
  const int m0 = wm*32;

  float accD[2][8][4], accGi[2][4][4], accGh[2][4][4];
  #pragma unroll
  for (int i = 0; i < 2; i++) {
    #pragma unroll
    for (int j = 0; j < 8; j++)
      #pragma unroll
      for (int e = 0; e < 4; e++) accD[i][j][e] = 0.f;
    #pragma unroll
    for (int j = 0; j < 4; j++)
      #pragma unroll
      for (int e = 0; e < 4; e++) { accGi[i][j][e] = 0.f; accGh[i][j][e] = 0.f; }
  }

  const uint32_t a_lane  = (uint32_t)((m0 + (lane & 15))*GP + (lane >> 4)*16);
  const uint32_t bD_lane = (uint32_t)((g*64 + ((lane >> 4) << 3) + (lane & 7))*RBP + ((lane >> 3) & 1)*16);
  const uint32_t bN_lane = (uint32_t)((256 + g*32 + ((lane >> 4) << 3) + (lane & 7))*RBP + ((lane >> 3) & 1)*16);
  const uint32_t bhBase[2] = {R_BH0, R_BH1};

  // B source helper: chunk q -> image
  const __nv_bfloat16* bsrc_hi[4] = {g_Wihimg, g_Wihimg + 49152, g_Whhimg, g_Whhimg + 49152};

  // Preamble: Bh(0), Bl(0), Bh(1); then A(phase 0)
  gru_issueB(bsrc_hi[0],          sb, R_BH0, t);
  gru_issueB(bsrc_hi[0] + 24576,  sb, R_BL,  t);
  gru_issueB(bsrc_hi[1],          sb, R_BH1, t);
  gru_loadA(st3, row0, smem, t);

  #pragma unroll
  for (int q = 0; q < 4; q++) {
    const int p = q >> 1, c = q & 1;
    // head wait: Bh(q) ready
    if (q < 3) { CP_WAIT(2); } else { CP_WAIT(1); }
    __syncthreads();
    if (q == 2) {            // phase 1: reload A from feat
      gru_loadA(feat, row0, smem, t);
      __syncthreads();
    }
    float (*accN)[4][4] = p ? accGh : accGi;
    const uint32_t aK = (uint32_t)(c * 128);  // k-chunk offset in A (64 cols * 2B)

    // passes 1,2: Ah*Bh, Al*Bh
    #pragma unroll
    for (int pass = 0; pass < 2; pass++) {
      uint32_t ab  = sb + (pass ? R_ALO : R_AHI) + a_lane + aK;
      uint32_t bbD = sb + bhBase[c] + bD_lane;
      uint32_t bbN = sb + bhBase[c] + bN_lane;
      #pragma unroll
      for (int ks = 0; ks < 4; ks++) {
        uint32_t a0[4], a1[4];
        ldsm4(a0, ab + ks*32);
        ldsm4(a1, ab + 16*GP + ks*32);
        #pragma unroll
        for (int np = 0; np < 4; np++) {
          uint32_t b4[4];
          ldsm4(b4, bbD + np*16*RBP + ks*32);
          mma16816(accD[0][np*2],   a0, b4);
          mma16816(accD[0][np*2+1], a0, b4+2);
          mma16816(accD[1][np*2],   a1, b4);
          mma16816(accD[1][np*2+1], a1, b4+2);
        }
        #pragma unroll
        for (int np = 0; np < 2; np++) {
          uint32_t b4[4];
          ldsm4(b4, bbN + np*16*RBP + ks*32);
          mma16816(accN[0][np*2],   a0, b4);
          mma16816(accN[0][np*2+1], a0, b4+2);
          mma16816(accN[1][np*2],   a1, b4);
          mma16816(accN[1][np*2+1], a1, b4+2);
        }
      }
    }
    // Bl(q) ready
    if (q < 3) { CP_WAIT(1); } else { CP_WAIT(0); }
    __syncthreads();
    // pass 3: Ah*Bl
    {
      uint32_t ab  = sb + R_AHI + a_lane + aK;
      uint32_t bbD = sb + R_BL + bD_lane;
      uint32_t bbN = sb + R_BL + bN_lane;
      #pragma unroll
      for (int ks = 0; ks < 4; ks++) {
        uint32_t a0[4], a1[4];
        ldsm4(a0, ab + ks*32);
        ldsm4(a1, ab + 16*GP + ks*32);
        #pragma unroll
        for (int np = 0; np < 4; np++) {
          uint32_t b4[4];
          ldsm4(b4, bbD + np*16*RBP + ks*32);
          mma16816(accD[0][np*2],   a0, b4);
          mma16816(accD[0][np*2+1], a0, b4+2);
          mma16816(accD[1][np*2],   a1, b4);
          mma16816(accD[1][np*2+1], a1, b4+2);
        }
        #pragma unroll
        for (int np = 0; np < 2; np++) {
          uint32_t b4[4];
          ldsm4(b4, bbN + np*16*RBP + ks*32);
          mma16816(accN[0][np*2],   a0, b4);
          mma16816(accN[0][np*2+1], a0, b4+2);
          mma16816(accN[1][np*2],   a1, b4);
          mma16816(accN[1][np*2+1], a1, b4+2);
        }
      }
    }
    __syncthreads();
    // tail prefetches: Bl(q+1), then Bh(q+2)
    if (q < 3) gru_issueB(bsrc_hi[q+1] + 24576, sb, R_BL, t);
    if (q < 2) gru_issueB(bsrc_hi[q+2], sb, bhBase[c], t);
  }

  // ---- stage accumulators to smem (overlays B buffers) ----
  __syncthreads();
  {
    const int r_lo = lane >> 2, c_off = (lane & 3)*2;
    float* base = (float*)(smem + R_STAG);
    // dense -> R/Z planes
    #pragma unroll
    for (int mt = 0; mt < 2; mt++) {
      #pragma unroll
      for (int nt = 0; nt < 8; nt++) {
        int C = g*64 + nt*8 + c_off;
        float* plane = base + (C >> 7)*64*132;
        int col = C & 127;
        int row = m0 + mt*16 + r_lo;
        *(float2*)(plane + row*132 + col)     = make_float2(accD[mt][nt][0], accD[mt][nt][1]);
        *(float2*)(plane + (row+8)*132 + col) = make_float2(accD[mt][nt][2], accD[mt][nt][3]);
      }
    }
    // gi / gh planes
    #pragma unroll
    for (int mt = 0; mt < 2; mt++) {
      #pragma unroll
      for (int nt = 0; nt < 4; nt++) {
        int col = g*32 + nt*8 + c_off;
        int row = m0 + mt*16 + r_lo;
        float* pGi = base + 2*64*132;
        float* pGh = base + 3*64*132;
        *(float2*)(pGi + row*132 + col)     = make_float2(accGi[mt][nt][0], accGi[mt][nt][1]);
        *(float2*)(pGi + (row+8)*132 + col) = make_float2(accGi[mt][nt][2], accGi[mt][nt][3]);
        *(float2*)(pGh + row*132 + col)     = make_float2(accGh[mt][nt][0], accGh[mt][nt][1]);
        *(float2*)(pGh + (row+8)*132 + col) = make_float2(accGh[mt][nt][2], accGh[mt][nt][3]);
      }
    }
  }
  __syncthreads();

  // ---- epilogue: combine gates, GRU nonlinearity, residual ----
  const float* pR  = (const float*)(smem + R_STAG);
  const float* pZ  = pR + 64*132;
  const float* pGi = pR + 2*64*132;
  const float* pGh = pR + 3*64*132;
  #pragma unroll
  for (int it = 0; it < 8; it++) {
    int idx = it*1024 + t*4;
    int row = idx >> 7, col = idx & 127;
    int so = row*132 + col;
    float4 rv = *(const float4*)(pR + so);
    float4 zv = *(const float4*)(pZ + so);
    float4 gi = *(const float4*)(pGi + so);
    float4 gh = *(const float4*)(pGh + so);
    float4 hv = *(const float4*)(feat + (size_t)(row0 + row)*HH + col);
    float rr[4] = {rv.x, rv.y, rv.z, rv.w};
    float zz[4] = {zv.x, zv.y, zv.z, zv.w};
    float gg[4] = {gi.x, gi.y, gi.z, gi.w};
    float hh2[4] = {gh.x, gh.y, gh.z, gh.w};
    float hx[4] = {hv.x, hv.y, hv.z, hv.w};
    float ox[4];
    #pragma unroll
    for (int e = 0; e < 4; e++) {
      int j = col + e;
      float r_ = rr[e] + __ldg(b_ih + j)       + __ldg(b_hh + j);
      float z_ = zz[e] + __ldg(b_ih + 128 + j) + __ldg(b_hh + 128 + j);
      float gi_ = gg[e]  + __ldg(b_ih + 256 + j);
      float gh_ = hh2[e] + __ldg(b_hh + 256 + j);
      float rs_ = 1.f / (1.f + __expf(-r_));
      float zs_ = 1.f / (1.f + __expf(-z_));
      float tx = gi_ + rs_ * gh_;
      float et = __expf(2.f * tx);
      float nn = 1.f - 2.f / (et + 1.f);
      float h = hx[e];
      ox[e] = h + nn + zs_ * (h - nn);
    }
    *(float4*)(out + (size_t)(row0 + row)*HH + col) = make_float4(ox[0], ox[1], ox[2], ox[3]);
  }
}

// ---------------------------------------------------------------------------
extern "C" void kernel_launch(void* const* d_in, const int* in_sizes, int n_in,
                              void* d_out, int out_size) {
  (void)in_sizes; (void)n_in; (void)out_size;
  const float* feat = (const float*)d_in[0];
  const float* W1   = (const float*)d_in[1];
  const float* b1   = (const float*)d_in[2];
  const float* W3   = (const float*)d_in[3];
  const float* b3   = (const float*)d_in[4];
  const float* Wih  = (const float*)d_in[5];
  const float* bih  = (const float*)d_in[6];
  const float* Whh  = (const float*)d_in[7];
  const float* bhh  = (const float*)d_in[8];
  float* out = (float*)d_out;

  float *st1, *st3, *rs;
  __nv_bfloat16 *w1i, *w3i;
  cudaGetSymbolAddress((void**)&st1, g_state1);
  cudaGetSymbolAddress((void**)&st3, g_state3);
  cudaGetSymbolAddress((void**)&rs,  g_rowsum);
  cudaGetSymbolAddress((void**)&w1i, g_W1img);
  cudaGetSymbolAddress((void**)&w3i, g_W3img);

  cudaFuncSetAttribute(gemm_s_mma, cudaFuncAttributeMaxDynamicSharedMemorySize, G_SMEM);
  cudaFuncSetAttribute(gru_mma,    cudaFuncAttributeMaxDynamicSharedMemorySize, R_SMEM);

  prep_kernel<<<2048, 256>>>(W1, W3, Wih, Whh);
  gemm_s_mma<<<dim3(BB/128, SS), 256, G_SMEM>>>(feat, nullptr, w1i, b1, st1);
  rowsum_kernel<<<(BB*32)/256, 256>>>(st1, rs);
  gemm_s_mma<<<dim3(BB/128, SS), 256, G_SMEM>>>(st1, rs, w3i, b3, st3);
  gru_mma<<<NROWS/64, 256, R_SMEM>>>(feat, st3, bih, bhh, out);
}

// round 11
// speedup vs baseline: 1.0008x; 1.0008x over previous
#include <cuda_runtime.h>
#include <cuda_bf16.h>
#include <math.h>
#include <stdint.h>

#define BB 4096
#define SS 64
#define HH 128
#define NROWS (BB*SS)

// ---------------------------------------------------------------------------
// Device scratch
// ---------------------------------------------------------------------------
__device__ float g_state1[NROWS*HH];
__device__ float g_state3[NROWS*HH];
__device__ float g_rowsum[BB*HH];
__device__ __align__(16) __nv_bfloat16 g_W1img[SS*2*16384];   // [s][hi/lo][o=128][k=128]
__device__ __align__(16) __nv_bfloat16 g_W3img[SS*2*16384];
__device__ __align__(16) __nv_bfloat16 g_Wihimg[2*2*24576];   // [kchunk][hi/lo][n=384][k=64]
__device__ __align__(16) __nv_bfloat16 g_Whhimg[2*2*24576];

__device__ __forceinline__ uint32_t smem_u32(const void* p) {
  uint32_t a;
  asm("{ .reg .u64 t; cvta.to.shared.u64 t, %1; cvt.u32.u64 %0, t; }" : "=r"(a) : "l"(p));
  return a;
}
__device__ __forceinline__ void ldsm4(uint32_t* r, uint32_t addr) {
  asm volatile("ldmatrix.sync.aligned.m8n8.x4.shared.b16 {%0,%1,%2,%3}, [%4];"
               : "=r"(r[0]), "=r"(r[1]), "=r"(r[2]), "=r"(r[3]) : "r"(addr));
}
__device__ __forceinline__ void mma16816(float* d, const uint32_t* a, const uint32_t* b) {
  asm volatile(
    "mma.sync.aligned.m16n8k16.row.col.f32.bf16.bf16.f32 "
    "{%0,%1,%2,%3}, {%4,%5,%6,%7}, {%8,%9}, {%0,%1,%2,%3};"
    : "+f"(d[0]), "+f"(d[1]), "+f"(d[2]), "+f"(d[3])
    : "r"(a[0]), "r"(a[1]), "r"(a[2]), "r"(a[3]), "r"(b[0]), "r"(b[1]));
}
__device__ __forceinline__ void split8(const float* v, uint4& hiq, uint4& loq) {
  __nv_bfloat16 hv[8], lv[8];
  #pragma unroll
  for (int j = 0; j < 8; j++) {
    hv[j] = __float2bfloat16(v[j]);
    lv[j] = __float2bfloat16(v[j] - __bfloat162float(hv[j]));
  }
  hiq = *(uint4*)hv; loq = *(uint4*)lv;
}
__device__ __forceinline__ void cpasync16(uint32_t dst, const void* src) {
  asm volatile("cp.async.cg.shared.global [%0], [%1], 16;" :: "r"(dst), "l"(src));
}
#define CP_COMMIT() asm volatile("cp.async.commit_group;" ::: "memory")
#define CP_WAIT(n)  asm volatile("cp.async.wait_group %0;" :: "n"(n) : "memory")

// ---------------------------------------------------------------------------
// Prep: split weights into bf16 hi/lo
// ---------------------------------------------------------------------------
__global__ void prep_kernel(const float* __restrict__ W1, const float* __restrict__ W3,
                            const float* __restrict__ Wih, const float* __restrict__ Whh) {
  const int total1 = SS * 128 * 128;
  for (int idx = blockIdx.x * blockDim.x + threadIdx.x; idx < total1;
       idx += gridDim.x * blockDim.x) {
    int s = idx >> 14, r = idx & 16383;
    float w = W1[idx];
    __nv_bfloat16 h = __float2bfloat16(w);
    g_W1img[s*32768 + r]         = h;
    g_W1img[s*32768 + 16384 + r] = __float2bfloat16(w - __bfloat162float(h));
    w = W3[idx];
    h = __float2bfloat16(w);
    g_W3img[s*32768 + r]         = h;
    g_W3img[s*32768 + 16384 + r] = __float2bfloat16(w - __bfloat162float(h));
  }
  const int total2 = 384 * 128;
  for (int idx = blockIdx.x * blockDim.x + threadIdx.x; idx < total2;
       idx += gridDim.x * blockDim.x) {
    int j = idx >> 7, k = idx & 127;
    int c = k >> 6, kc = k & 63;
    int o = j*64 + kc;
    float w = Wih[idx];
    __nv_bfloat16 h = __float2bfloat16(w);
    g_Wihimg[c*49152 + o]         = h;
    g_Wihimg[c*49152 + 24576 + o] = __float2bfloat16(w - __bfloat162float(h));
    w = Whh[idx];
    h = __float2bfloat16(w);
    g_Whhimg[c*49152 + o]         = h;
    g_Whhimg[c*49152 + 24576 + o] = __float2bfloat16(w - __bfloat162float(h));
  }
}

// ---------------------------------------------------------------------------
// K1/K3: per-s GEMM via mma.sync (B via cp.async overlapped with A split)
// ---------------------------------------------------------------------------
#define GP 272
#define G_AHI 0
#define G_ALO (128*GP)
#define G_BHI (2*128*GP)
#define G_BLO (3*128*GP)
#define G_SMEM (4*128*GP)

__global__ __launch_bounds__(256, 1)
void gemm_s_mma(const float* __restrict__ in, const float* __restrict__ rowsum,
                const __nv_bfloat16* __restrict__ Wimg, const float* __restrict__ bias,
                float* __restrict__ out) {
  extern __shared__ char smem[];
  const uint32_t sb = smem_u32(smem);
  const int s = blockIdx.y, b0 = blockIdx.x * 128, t = threadIdx.x;
  const int wid = t >> 5, lane = t & 31;

  // ---- B via cp.async (overlaps with A work below) ----
  {
    const __nv_bfloat16* whi = Wimg + (size_t)s * 32768;
    #pragma unroll
    for (int i = 0; i < 8; i++) {
      int ci = i*256 + t;
      int row = ci >> 4, kq = ci & 15;
      cpasync16(sb + G_BHI + row*GP + kq*16, whi + row*128 + kq*8);
      cpasync16(sb + G_BLO + row*GP + kq*16, whi + 16384 + row*128 + kq*8);
    }
    CP_COMMIT();
  }
  // ---- A load (fp32), split hi/lo ----
  #pragma unroll
  for (int i = 0; i < 8; i++) {
    int ci = i*256 + t;
    int row = ci >> 4, kq = ci & 15, k0 = kq*8;
    const float* src = in + (size_t)(b0 + row)*SS*HH + s*HH + k0;
    float v[8];
    float4 a0 = *(const float4*)src, a1 = *(const float4*)(src + 4);
    v[0]=a0.x; v[1]=a0.y; v[2]=a0.z; v[3]=a0.w; v[4]=a1.x; v[5]=a1.y; v[6]=a1.z; v[7]=a1.w;
    if (rowsum) {
      const float* rp = rowsum + (size_t)(b0 + row)*HH + k0;
      float4 r0 = __ldg((const float4*)rp), r1 = __ldg((const float4*)(rp + 4));
      v[0]=r0.x-v[0]; v[1]=r0.y-v[1]; v[2]=r0.z-v[2]; v[3]=r0.w-v[3];
      v[4]=r1.x-v[4]; v[5]=r1.y-v[5]; v[6]=r1.z-v[6]; v[7]=r1.w-v[7];
    }
    uint4 hq, lq;
    split8(v, hq, lq);
    *(uint4*)(smem + G_AHI + row*GP + kq*16) = hq;
    *(uint4*)(smem + G_ALO + row*GP + kq*16) = lq;
  }
  CP_WAIT(0);
  __syncthreads();

  // ---- MMA mainloop ----
  const int wm = wid >> 1, wn = wid & 1;
  const int m0 = wm*32, n0 = wn*64;
  float acc[2][8][4];
  #pragma unroll
  for (int i = 0; i < 2; i++)
    #pragma unroll
    for (int j = 0; j < 8; j++)
      #pragma unroll
      for (int e = 0; e < 4; e++) acc[i][j][e] = 0.f;

  const uint32_t aoffs[3] = {G_AHI, G_ALO, G_AHI};
  const uint32_t boffs[3] = {G_BHI, G_BHI, G_BLO};
  const uint32_t a_lane = (uint32_t)((m0 + (lane & 15))*GP + (lane >> 4)*16);
  const uint32_t b_lane = (uint32_t)((n0 + ((lane >> 4) << 3) + (lane & 7))*GP + ((lane >> 3) & 1)*16);

  #pragma unroll
  for (int pass = 0; pass < 3; pass++) {
    uint32_t ab = sb + aoffs[pass] + a_lane;
    uint32_t bb = sb + boffs[pass] + b_lane;
    #pragma unroll
    for (int ks = 0; ks < 8; ks++) {
      uint32_t a0[4], a1[4];
      ldsm4(a0, ab + ks*32);
      ldsm4(a1, ab + 16*GP + ks*32);
      #pragma unroll
      for (int np = 0; np < 4; np++) {
        uint32_t b4[4];
        ldsm4(b4, bb + np*16*GP + ks*32);
        mma16816(acc[0][np*2],   a0, b4);
        mma16816(acc[0][np*2+1], a0, b4+2);
        mma16816(acc[1][np*2],   a1, b4);
        mma16816(acc[1][np*2+1], a1, b4+2);
      }
    }
  }

  // ---- epilogue ----
  const int r_lo = lane >> 2, c_off = (lane & 3)*2;
  #pragma unroll
  for (int mt = 0; mt < 2; mt++) {
    #pragma unroll
    for (int nt = 0; nt < 8; nt++) {
      int col = n0 + nt*8 + c_off;
      float bv0 = __ldg(bias + s*HH + col);
      float bv1 = __ldg(bias + s*HH + col + 1);
      int row = b0 + m0 + mt*16 + r_lo;
      float* op = out + (size_t)row*SS*HH + s*HH + col;
      *(float2*)op = make_float2(acc[mt][nt][0] + bv0, acc[mt][nt][1] + bv1);
      op += (size_t)8*SS*HH;
      *(float2*)op = make_float2(acc[mt][nt][2] + bv0, acc[mt][nt][3] + bv1);
    }
  }
}

// ---------------------------------------------------------------------------
// K2: rowsum
// ---------------------------------------------------------------------------
__global__ void rowsum_kernel(const float* __restrict__ st1, float* __restrict__ rs) {
  int idx = blockIdx.x*blockDim.x + threadIdx.x;
  int b = idx >> 5, h4 = (idx & 31)*4;
  const float* p = st1 + (size_t)b*SS*HH + h4;
  float4 a = make_float4(0.f,0.f,0.f,0.f);
  #pragma unroll 8
  for (int s = 0; s < SS; s++) {
    float4 v = __ldg((const float4*)(p + (size_t)s*HH));
    a.x += v.x; a.y += v.y; a.z += v.z; a.w += v.w;
  }
  *(float4*)(rs + (size_t)b*HH + h4) = a;
}

// ---------------------------------------------------------------------------
// K4: fused GRU, balanced warps + cp.async pipelined B.
// 8 warps = 2 rowgroups x 4 "g" warps. Warp g handles:
//   dense RZ cols [g*64, g*64+64)  (both phases, K=128 each)
//   gi cols [g*32, g*32+32) in phase 0;  gh cols [g*32..) in phase 1
// B buffers: Bh x2 (double-buffered), Bl x1.
// Chunk q = phase*2 + kchunk; passes: (Ah,Bh),(Al,Bh),(Ah,Bl).
// ---------------------------------------------------------------------------
#define RBP 144
#define R_AHI 0
#define R_ALO 17408
#define R_BH0 34816
#define R_BH1 90112
#define R_BL  145408
#define R_STAG 34816
#define R_SMEM 200704

__device__ __forceinline__ void gru_loadA(const float* __restrict__ src, int row0,
                                          char* smem, int t) {
  #pragma unroll
  for (int i = 0; i < 4; i++) {
    int ci = i*256 + t;
    int row = ci >> 4, kq = ci & 15;
    const float* sp = src + (size_t)(row0 + row)*HH + kq*8;
    float v[8];
    float4 x0 = *(const float4*)sp, x1 = *(const float4*)(sp + 4);
    v[0]=x0.x; v[1]=x0.y; v[2]=x0.z; v[3]=x0.w; v[4]=x1.x; v[5]=x1.y; v[6]=x1.z; v[7]=x1.w;
    uint4 hq, lq;
    split8(v, hq, lq);
    *(uint4*)(smem + R_AHI + row*GP + kq*16) = hq;
    *(uint4*)(smem + R_ALO + row*GP + kq*16) = lq;
  }
}
// issue one 384x64 bf16 image (hi or lo) into padded smem via cp.async
__device__ __forceinline__ void gru_issueB(const __nv_bfloat16* __restrict__ src,
                                           uint32_t sb, uint32_t dstBase, int t) {
  #pragma unroll
  for (int i = 0; i < 12; i++) {
    int ci = i*256 + t;
    int row = ci >> 3, kq = ci & 7;
    cpasync16(sb + dstBase + row*RBP + kq*16, src + row*64 + kq*8);
  }
  CP_COMMIT();
}

__global__ __launch_bounds__(256, 1)
void gru_mma(const float* __restrict__ feat, const float* __restrict__ st3,
             const float* __restrict__ b_ih, const float* __restrict__ b_hh,
             float* __restrict__ out) {
  extern __shared__ char smem[];
  const uint32_t sb = smem_u32(smem);
  const int row0 = blockIdx.x * 64, t = threadIdx.x;
  const int wid = t >> 5, lane = t & 31;
  const int wm = wid >> 2, g = wid & 3;
  const int m0 = wm*32;

  float accD[2][8][4], accGi[2][4][4], accGh[2][4][4];
  #pragma unroll
  for (int i = 0; i < 2; i++) {
    #pragma unroll
    for (int j = 0; j < 8; j++)
      #pragma unroll
      for (int e = 0; e < 4; e++) accD[i][j][e] = 0.f;
    #pragma unroll
    for (int j = 0; j < 4; j++)
      #pragma unroll
      for (int e = 0; e < 4; e++) { accGi[i][j][e] = 0.f; accGh[i][j][e] = 0.f; }
  }

  const uint32_t a_lane  = (uint32_t)((m0 + (lane & 15))*GP + (lane >> 4)*16);
  const uint32_t bD_lane = (uint32_t)((g*64 + ((lane >> 4) << 3) + (lane & 7))*RBP + ((lane >> 3) & 1)*16);
  const uint32_t bN_lane = (uint32_t)((256 + g*32 + ((lane >> 4) << 3) + (lane & 7))*RBP + ((lane >> 3) & 1)*16);
  const uint32_t bhBase[2] = {R_BH0, R_BH1};

  // B source helper: chunk q -> image
  const __nv_bfloat16* bsrc_hi[4] = {g_Wihimg, g_Wihimg + 49152, g_Whhimg, g_Whhimg + 49152};

  // Preamble: Bh(0), Bl(0), Bh(1); then A(phase 0)
  gru_issueB(bsrc_hi[0],          sb, R_BH0, t);
  gru_issueB(bsrc_hi[0] + 24576,  sb, R_BL,  t);
  gru_issueB(bsrc_hi[1],          sb, R_BH1, t);
  gru_loadA(st3, row0, smem, t);

  #pragma unroll
  for (int q = 0; q < 4; q++) {
    const int p = q >> 1, c = q & 1;
    // head wait: Bh(q) ready
    if (q < 3) { CP_WAIT(2); } else { CP_WAIT(1); }
    __syncthreads();
    if (q == 2) {            // phase 1: reload A from feat
      gru_loadA(feat, row0, smem, t);
      __syncthreads();
    }
    float (*accN)[4][4] = p ? accGh : accGi;
    const uint32_t aK = (uint32_t)(c * 128);  // k-chunk offset in A (64 cols * 2B)

    // passes 1,2: Ah*Bh, Al*Bh
    #pragma unroll
    for (int pass = 0; pass < 2; pass++) {
      uint32_t ab  = sb + (pass ? R_ALO : R_AHI) + a_lane + aK;
      uint32_t bbD = sb + bhBase[c] + bD_lane;
      uint32_t bbN = sb + bhBase[c] + bN_lane;
      #pragma unroll
      for (int ks = 0; ks < 4; ks++) {
        uint32_t a0[4], a1[4];
        ldsm4(a0, ab + ks*32);
        ldsm4(a1, ab + 16*GP + ks*32);
        #pragma unroll
        for (int np = 0; np < 4; np++) {
          uint32_t b4[4];
          ldsm4(b4, bbD + np*16*RBP + ks*32);
          mma16816(accD[0][np*2],   a0, b4);
          mma16816(accD[0][np*2+1], a0, b4+2);
          mma16816(accD[1][np*2],   a1, b4);
          mma16816(accD[1][np*2+1], a1, b4+2);
        }
        #pragma unroll
        for (int np = 0; np < 2; np++) {
          uint32_t b4[4];
          ldsm4(b4, bbN + np*16*RBP + ks*32);
          mma16816(accN[0][np*2],   a0, b4);
          mma16816(accN[0][np*2+1], a0, b4+2);
          mma16816(accN[1][np*2],   a1, b4);
          mma16816(accN[1][np*2+1], a1, b4+2);
        }
      }
    }
    // Bl(q) ready
    if (q < 3) { CP_WAIT(1); } else { CP_WAIT(0); }
    __syncthreads();
    // pass 3: Ah*Bl
    {
      uint32_t ab  = sb + R_AHI + a_lane + aK;
      uint32_t bbD = sb + R_BL + bD_lane;
      uint32_t bbN = sb + R_BL + bN_lane;
      #pragma unroll
      for (int ks = 0; ks < 4; ks++) {
        uint32_t a0[4], a1[4];
        ldsm4(a0, ab + ks*32);
        ldsm4(a1, ab + 16*GP + ks*32);
        #pragma unroll
        for (int np = 0; np < 4; np++) {
          uint32_t b4[4];
          ldsm4(b4, bbD + np*16*RBP + ks*32);
          mma16816(accD[0][np*2],   a0, b4);
          mma16816(accD[0][np*2+1], a0, b4+2);
          mma16816(accD[1][np*2],   a1, b4);
          mma16816(accD[1][np*2+1], a1, b4+2);
        }
        #pragma unroll
        for (int np = 0; np < 2; np++) {
          uint32_t b4[4];
          ldsm4(b4, bbN + np*16*RBP + ks*32);
          mma16816(accN[0][np*2],   a0, b4);
          mma16816(accN[0][np*2+1], a0, b4+2);
          mma16816(accN[1][np*2],   a1, b4);
          mma16816(accN[1][np*2+1], a1, b4+2);
        }
      }
    }
    __syncthreads();
    // tail prefetches: Bl(q+1), then Bh(q+2)
    if (q < 3) gru_issueB(bsrc_hi[q+1] + 24576, sb, R_BL, t);
    if (q < 2) gru_issueB(bsrc_hi[q+2], sb, bhBase[c], t);
  }

  // ---- stage accumulators to smem (overlays B buffers) ----
  __syncthreads();
  {
    const int r_lo = lane >> 2, c_off = (lane & 3)*2;
    float* base = (float*)(smem + R_STAG);
    // dense -> R/Z planes
    #pragma unroll
    for (int mt = 0; mt < 2; mt++) {
      #pragma unroll
      for (int nt = 0; nt < 8; nt++) {
        int C = g*64 + nt*8 + c_off;
        float* plane = base + (C >> 7)*64*132;
        int col = C & 127;
        int row = m0 + mt*16 + r_lo;
        *(float2*)(plane + row*132 + col)     = make_float2(accD[mt][nt][0], accD[mt][nt][1]);
        *(float2*)(plane + (row+8)*132 + col) = make_float2(accD[mt][nt][2], accD[mt][nt][3]);
      }
    }
    // gi / gh planes
    #pragma unroll
    for (int mt = 0; mt < 2; mt++) {
      #pragma unroll
      for (int nt = 0; nt < 4; nt++) {
        int col = g*32 + nt*8 + c_off;
        int row = m0 + mt*16 + r_lo;
        float* pGi = base + 2*64*132;
        float* pGh = base + 3*64*132;
        *(float2*)(pGi + row*132 + col)     = make_float2(accGi[mt][nt][0], accGi[mt][nt][1]);
        *(float2*)(pGi + (row+8)*132 + col) = make_float2(accGi[mt][nt][2], accGi[mt][nt][3]);
        *(float2*)(pGh + row*132 + col)     = make_float2(accGh[mt][nt][0], accGh[mt][nt][1]);
        *(float2*)(pGh + (row+8)*132 + col) = make_float2(accGh[mt][nt][2], accGh[mt][nt][3]);
      }
    }
  }
  __syncthreads();

  // ---- epilogue: combine gates, GRU nonlinearity, residual ----
  const float* pR  = (const float*)(smem + R_STAG);
  const float* pZ  = pR + 64*132;
  const float* pGi = pR + 2*64*132;
  const float* pGh = pR + 3*64*132;
  #pragma unroll
  for (int it = 0; it < 8; it++) {
    int idx = it*1024 + t*4;
    int row = idx >> 7, col = idx & 127;
    int so = row*132 + col;
    float4 rv = *(const float4*)(pR + so);
    float4 zv = *(const float4*)(pZ + so);
    float4 gi = *(const float4*)(pGi + so);
    float4 gh = *(const float4*)(pGh + so);
    float4 hv = *(const float4*)(feat + (size_t)(row0 + row)*HH + col);
    float rr[4] = {rv.x, rv.y, rv.z, rv.w};
    float zz[4] = {zv.x, zv.y, zv.z, zv.w};
    float gg[4] = {gi.x, gi.y, gi.z, gi.w};
    float hh2[4] = {gh.x, gh.y, gh.z, gh.w};
    float hx[4] = {hv.x, hv.y, hv.z, hv.w};
    float ox[4];
    #pragma unroll
    for (int e = 0; e < 4; e++) {
      int j = col + e;
      float r_ = rr[e] + __ldg(b_ih + j)       + __ldg(b_hh + j);
      float z_ = zz[e] + __ldg(b_ih + 128 + j) + __ldg(b_hh + 128 + j);
      float gi_ = gg[e]  + __ldg(b_ih + 256 + j);
      float gh_ = hh2[e] + __ldg(b_hh + 256 + j);
      float rs_ = 1.f / (1.f + __expf(-r_));
      float zs_ = 1.f / (1.f + __expf(-z_));
      float tx = gi_ + rs_ * gh_;
      float et = __expf(2.f * tx);
      float nn = 1.f - 2.f / (et + 1.f);
      float h = hx[e];
      ox[e] = h + nn + zs_ * (h - nn);
    }
    *(float4*)(out + (size_t)(row0 + row)*HH + col) = make_float4(ox[0], ox[1], ox[2], ox[3]);
  }
}

// ---------------------------------------------------------------------------
extern "C" void kernel_launch(void* const* d_in, const int* in_sizes, int n_in,
                              void* d_out, int out_size) {
  (void)in_sizes; (void)n_in; (void)out_size;
  const float* feat = (const float*)d_in[0];
  const float* W1   = (const float*)d_in[1];
  const float* b1   = (const float*)d_in[2];
  const float* W3   = (const float*)d_in[3];
  const float* b3   = (const float*)d_in[4];
  const float* Wih  = (const float*)d_in[5];
  const float* bih  = (const float*)d_in[6];
  const float* Whh  = (const float*)d_in[7];
  const float* bhh  = (const float*)d_in[8];
  float* out = (float*)d_out;

  float *st1, *st3, *rs;
  __nv_bfloat16 *w1i, *w3i;
  cudaGetSymbolAddress((void**)&st1, g_state1);
  cudaGetSymbolAddress((void**)&st3, g_state3);
  cudaGetSymbolAddress((void**)&rs,  g_rowsum);
  cudaGetSymbolAddress((void**)&w1i, g_W1img);
  cudaGetSymbolAddress((void**)&w3i, g_W3img);

  cudaFuncSetAttribute(gemm_s_mma, cudaFuncAttributeMaxDynamicSharedMemorySize, G_SMEM);
  cudaFuncSetAttribute(gru_mma,    cudaFuncAttributeMaxDynamicSharedMemorySize, R_SMEM);

  prep_kernel<<<2048, 256>>>(W1, W3, Wih, Whh);
  gemm_s_mma<<<dim3(BB/128, SS), 256, G_SMEM>>>(feat, nullptr, w1i, b1, st1);
  rowsum_kernel<<<(BB*32)/256, 256>>>(st1, rs);
  gemm_s_mma<<<dim3(BB/128, SS), 256, G_SMEM>>>(st1, rs, w3i, b3, st3);
  gru_mma<<<NROWS/64, 256, R_SMEM>>>(feat, st3, bih, bhh, out);
}

// round 12
// speedup vs baseline: 1.0023x; 1.0015x over previous
#include <cuda_runtime.h>
#include <cuda_bf16.h>
#include <math.h>
#include <stdint.h>

#define BB 4096
#define SS 64
#define HH 128
#define NROWS (BB*SS)

// ---------------------------------------------------------------------------
// Device scratch
// ---------------------------------------------------------------------------
__device__ float g_state1[NROWS*HH];
__device__ float g_state3[NROWS*HH];
__device__ float g_rowsum[BB*HH];
__device__ __align__(16) __nv_bfloat16 g_W1img[SS*2*16384];   // [s][hi/lo][o=128][k=128]
__device__ __align__(16) __nv_bfloat16 g_W3img[SS*2*16384];
__device__ __align__(16) __nv_bfloat16 g_Wihimg[2*2*24576];   // [kchunk][hi/lo][n=384][k=64]
__device__ __align__(16) __nv_bfloat16 g_Whhimg[2*2*24576];

__device__ __forceinline__ uint32_t smem_u32(const void* p) {
  uint32_t a;
  asm("{ .reg .u64 t; cvta.to.shared.u64 t, %1; cvt.u32.u64 %0, t; }" : "=r"(a) : "l"(p));
  return a;
}
__device__ __forceinline__ void ldsm4(uint32_t* r, uint32_t addr) {
  asm volatile("ldmatrix.sync.aligned.m8n8.x4.shared.b16 {%0,%1,%2,%3}, [%4];"
               : "=r"(r[0]), "=r"(r[1]), "=r"(r[2]), "=r"(r[3]) : "r"(addr));
}
__device__ __forceinline__ void mma16816(float* d, const uint32_t* a, const uint32_t* b) {
  asm volatile(
    "mma.sync.aligned.m16n8k16.row.col.f32.bf16.bf16.f32 "
    "{%0,%1,%2,%3}, {%4,%5,%6,%7}, {%8,%9}, {%0,%1,%2,%3};"
    : "+f"(d[0]), "+f"(d[1]), "+f"(d[2]), "+f"(d[3])
    : "r"(a[0]), "r"(a[1]), "r"(a[2]), "r"(a[3]), "r"(b[0]), "r"(b[1]));
}
__device__ __forceinline__ void split8(const float* v, uint4& hiq, uint4& loq) {
  __nv_bfloat16 hv[8], lv[8];
  #pragma unroll
  for (int j = 0; j < 8; j++) {
    hv[j] = __float2bfloat16(v[j]);
    lv[j] = __float2bfloat16(v[j] - __bfloat162float(hv[j]));
  }
  hiq = *(uint4*)hv; loq = *(uint4*)lv;
}
__device__ __forceinline__ void cpasync16(uint32_t dst, const void* src) {
  asm volatile("cp.async.cg.shared.global [%0], [%1], 16;" :: "r"(dst), "l"(src));
}
#define CP_COMMIT() asm volatile("cp.async.commit_group;" ::: "memory")
#define CP_WAIT(n)  asm volatile("cp.async.wait_group %0;" :: "n"(n) : "memory")

// ---------------------------------------------------------------------------
// Prep: split weights into bf16 hi/lo
// ---------------------------------------------------------------------------
__global__ void prep_kernel(const float* __restrict__ W1, const float* __restrict__ W3,
                            const float* __restrict__ Wih, const float* __restrict__ Whh) {
  const int total1 = SS * 128 * 128;
  for (int idx = blockIdx.x * blockDim.x + threadIdx.x; idx < total1;
       idx += gridDim.x * blockDim.x) {
    int s = idx >> 14, r = idx & 16383;
    float w = W1[idx];
    __nv_bfloat16 h = __float2bfloat16(w);
    g_W1img[s*32768 + r]         = h;
    g_W1img[s*32768 + 16384 + r] = __float2bfloat16(w - __bfloat162float(h));
    w = W3[idx];
    h = __float2bfloat16(w);
    g_W3img[s*32768 + r]         = h;
    g_W3img[s*32768 + 16384 + r] = __float2bfloat16(w - __bfloat162float(h));
  }
  const int total2 = 384 * 128;
  for (int idx = blockIdx.x * blockDim.x + threadIdx.x; idx < total2;
       idx += gridDim.x * blockDim.x) {
    int j = idx >> 7, k = idx & 127;
    int c = k >> 6, kc = k & 63;
    int o = j*64 + kc;
    float w = Wih[idx];
    __nv_bfloat16 h = __float2bfloat16(w);
    g_Wihimg[c*49152 + o]         = h;
    g_Wihimg[c*49152 + 24576 + o] = __float2bfloat16(w - __bfloat162float(h));
    w = Whh[idx];
    h = __float2bfloat16(w);
    g_Whhimg[c*49152 + o]         = h;
    g_Whhimg[c*49152 + 24576 + o] = __float2bfloat16(w - __bfloat162float(h));
  }
}

// ---------------------------------------------------------------------------
// K1/K3: per-s GEMM via mma.sync (B via cp.async overlapped with A split)
// ---------------------------------------------------------------------------
#define GP 272
#define G_AHI 0
#define G_ALO (128*GP)
#define G_BHI (2*128*GP)
#define G_BLO (3*128*GP)
#define G_SMEM (4*128*GP)

__global__ __launch_bounds__(256, 1)
void gemm_s_mma(const float* __restrict__ in, const float* __restrict__ rowsum,
                const __nv_bfloat16* __restrict__ Wimg, const float* __restrict__ bias,
                float* __restrict__ out) {
  extern __shared__ char smem[];
  const uint32_t sb = smem_u32(smem);
  const int s = blockIdx.y, b0 = blockIdx.x * 128, t = threadIdx.x;
  const int wid = t >> 5, lane = t & 31;

  // ---- B via cp.async (overlaps with A work below) ----
  {
    const __nv_bfloat16* whi = Wimg + (size_t)s * 32768;
    #pragma unroll
    for (int i = 0; i < 8; i++) {
      int ci = i*256 + t;
      int row = ci >> 4, kq = ci & 15;
      cpasync16(sb + G_BHI + row*GP + kq*16, whi + row*128 + kq*8);
      cpasync16(sb + G_BLO + row*GP + kq*16, whi + 16384 + row*128 + kq*8);
    }
    CP_COMMIT();
  }
  // ---- A load (fp32), split hi/lo ----
  #pragma unroll
  for (int i = 0; i < 8; i++) {
    int ci = i*256 + t;
    int row = ci >> 4, kq = ci & 15, k0 = kq*8;
    const float* src = in + (size_t)(b0 + row)*SS*HH + s*HH + k0;
    float v[8];
    float4 a0 = *(const float4*)src, a1 = *(const float4*)(src + 4);
    v[0]=a0.x; v[1]=a0.y; v[2]=a0.z; v[3]=a0.w; v[4]=a1.x; v[5]=a1.y; v[6]=a1.z; v[7]=a1.w;
    if (rowsum) {
      const float* rp = rowsum + (size_t)(b0 + row)*HH + k0;
      float4 r0 = __ldg((const float4*)rp), r1 = __ldg((const float4*)(rp + 4));
      v[0]=r0.x-v[0]; v[1]=r0.y-v[1]; v[2]=r0.z-v[2]; v[3]=r0.w-v[3];
      v[4]=r1.x-v[4]; v[5]=r1.y-v[5]; v[6]=r1.z-v[6]; v[7]=r1.w-v[7];
    }
    uint4 hq, lq;
    split8(v, hq, lq);
    *(uint4*)(smem + G_AHI + row*GP + kq*16) = hq;
    *(uint4*)(smem + G_ALO + row*GP + kq*16) = lq;
  }
  CP_WAIT(0);
  __syncthreads();

  // ---- MMA mainloop ----
  const int wm = wid >> 1, wn = wid & 1;
  const int m0 = wm*32, n0 = wn*64;
  float acc[2][8][4];
  #pragma unroll
  for (int i = 0; i < 2; i++)
    #pragma unroll
    for (int j = 0; j < 8; j++)
      #pragma unroll
      for (int e = 0; e < 4; e++) acc[i][j][e] = 0.f;

  const uint32_t aoffs[3] = {G_AHI, G_ALO, G_AHI};
  const uint32_t boffs[3] = {G_BHI, G_BHI, G_BLO};
  const uint32_t a_lane = (uint32_t)((m0 + (lane & 15))*GP + (lane >> 4)*16);
  const uint32_t b_lane = (uint32_t)((n0 + ((lane >> 4) << 3) + (lane & 7))*GP + ((lane >> 3) & 1)*16);

  #pragma unroll
  for (int pass = 0; pass < 3; pass++) {
    uint32_t ab = sb + aoffs[pass] + a_lane;
    uint32_t bb = sb + boffs[pass] + b_lane;
    #pragma unroll
    for (int ks = 0; ks < 8; ks++) {
      uint32_t a0[4], a1[4];
      ldsm4(a0, ab + ks*32);
      ldsm4(a1, ab + 16*GP + ks*32);
      #pragma unroll
      for (int np = 0; np < 4; np++) {
        uint32_t b4[4];
        ldsm4(b4, bb + np*16*GP + ks*32);
        mma16816(acc[0][np*2],   a0, b4);
        mma16816(acc[0][np*2+1], a0, b4+2);
        mma16816(acc[1][np*2],   a1, b4);
        mma16816(acc[1][np*2+1], a1, b4+2);
      }
    }
  }

  // ---- epilogue ----
  const int r_lo = lane >> 2, c_off = (lane & 3)*2;
  #pragma unroll
  for (int mt = 0; mt < 2; mt++) {
    #pragma unroll
    for (int nt = 0; nt < 8; nt++) {
      int col = n0 + nt*8 + c_off;
      float bv0 = __ldg(bias + s*HH + col);
      float bv1 = __ldg(bias + s*HH + col + 1);
      int row = b0 + m0 + mt*16 + r_lo;
      float* op = out + (size_t)row*SS*HH + s*HH + col;
      *(float2*)op = make_float2(acc[mt][nt][0] + bv0, acc[mt][nt][1] + bv1);
      op += (size_t)8*SS*HH;
      *(float2*)op = make_float2(acc[mt][nt][2] + bv0, acc[mt][nt][3] + bv1);
    }
  }
}

// ---------------------------------------------------------------------------
// K2: rowsum
// ---------------------------------------------------------------------------
__global__ void rowsum_kernel(const float* __restrict__ st1, float* __restrict__ rs) {
  int idx = blockIdx.x*blockDim.x + threadIdx.x;
  int b = idx >> 5, h4 = (idx & 31)*4;
  const float* p = st1 + (size_t)b*SS*HH + h4;
  float4 a = make_float4(0.f,0.f,0.f,0.f);
  #pragma unroll 8
  for (int s = 0; s < SS; s++) {
    float4 v = __ldg((const float4*)(p + (size_t)s*HH));
    a.x += v.x; a.y += v.y; a.z += v.z; a.w += v.w;
  }
  *(float4*)(rs + (size_t)b*HH + h4) = a;
}

// ---------------------------------------------------------------------------
// K4: fused GRU, balanced warps + cp.async pipelined B.
// 8 warps = 2 rowgroups x 4 "g" warps. Warp g handles:
//   dense RZ cols [g*64, g*64+64)  (both phases, K=128 each)
//   gi cols [g*32, g*32+32) in phase 0;  gh cols [g*32..) in phase 1
// B buffers: Bh x2 (double-buffered), Bl x1.
// Chunk q = phase*2 + kchunk; passes: (Ah,Bh),(Al,Bh),(Ah,Bl).
// ---------------------------------------------------------------------------
#define RBP 144
#define R_AHI 0
#define R_ALO 17408
#define R_BH0 34816
#define R_BH1 90112
#define R_BL  145408
#define R_STAG 34816
#define R_SMEM 200704

__device__ __forceinline__ void gru_loadA(const float* __restrict__ src, int row0,
                                          char* smem, int t) {
  #pragma unroll
  for (int i = 0; i < 4; i++) {
    int ci = i*256 + t;
    int row = ci >> 4, kq = ci & 15;
    const float* sp = src + (size_t)(row0 + row)*HH + kq*8;
    float v[8];
    float4 x0 = *(const float4*)sp, x1 = *(const float4*)(sp + 4);
    v[0]=x0.x; v[1]=x0.y; v[2]=x0.z; v[3]=x0.w; v[4]=x1.x; v[5]=x1.y; v[6]=x1.z; v[7]=x1.w;
    uint4 hq, lq;
    split8(v, hq, lq);
    *(uint4*)(smem + R_AHI + row*GP + kq*16) = hq;
    *(uint4*)(smem + R_ALO + row*GP + kq*16) = lq;
  }
}
// issue one 384x64 bf16 image (hi or lo) into padded smem via cp.async
__device__ __forceinline__ void gru_issueB(const __nv_bfloat16* __restrict__ src,
                                           uint32_t sb, uint32_t dstBase, int t) {
  #pragma unroll
  for (int i = 0; i < 12; i++) {
    int ci = i*256 + t;
    int row = ci >> 3, kq = ci & 7;
    cpasync16(sb + dstBase + row*RBP + kq*16, src + row*64 + kq*8);
  }
  CP_COMMIT();
}

__global__ __launch_bounds__(256, 1)
void gru_mma(const float* __restrict__ feat, const float* __restrict__ st3,
             const float* __restrict__ b_ih, const float* __restrict__ b_hh,
             float* __restrict__ out) {
  extern __shared__ char smem[];
  const uint32_t sb = smem_u32(smem);
  const int row0 = blockIdx.x * 64, t = threadIdx.x;
  const int wid = t >> 5, lane = t & 31;
  const int wm = wid >> 2, g = wid & 3;
  const int m0 = wm*32;

  float accD[2][8][4], accGi[2][4][4], accGh[2][4][4];
  #pragma unroll
  for (int i = 0; i < 2; i++) {
    #pragma unroll
    for (int j = 0; j < 8; j++)
      #pragma unroll
      for (int e = 0; e < 4; e++) accD[i][j][e] = 0.f;
    #pragma unroll
    for (int j = 0; j < 4; j++)
      #pragma unroll
      for (int e = 0; e < 4; e++) { accGi[i][j][e] = 0.f; accGh[i][j][e] = 0.f; }
  }

  const uint32_t a_lane  = (uint32_t)((m0 + (lane & 15))*GP + (lane >> 4)*16);
  const uint32_t bD_lane = (uint32_t)((g*64 + ((lane >> 4) << 3) + (lane & 7))*RBP + ((lane >> 3) & 1)*16);
  const uint32_t bN_lane = (uint32_t)((256 + g*32 + ((lane >> 4) << 3) + (lane & 7))*RBP + ((lane >> 3) & 1)*16);
  const uint32_t bhBase[2] = {R_BH0, R_BH1};

  // B source helper: chunk q -> image
  const __nv_bfloat16* bsrc_hi[4] = {g_Wihimg, g_Wihimg + 49152, g_Whhimg, g_Whhimg + 49152};

  // Preamble: Bh(0), Bl(0), Bh(1); then A(phase 0)
  gru_issueB(bsrc_hi[0],          sb, R_BH0, t);
  gru_issueB(bsrc_hi[0] + 24576,  sb, R_BL,  t);
  gru_issueB(bsrc_hi[1],          sb, R_BH1, t);
  gru_loadA(st3, row0, smem, t);

  #pragma unroll
  for (int q = 0; q < 4; q++) {
    const int p = q >> 1, c = q & 1;
    // head wait: Bh(q) ready
    if (q < 3) { CP_WAIT(2); } else { CP_WAIT(1); }
    __syncthreads();
    if (q == 2) {            // phase 1: reload A from feat
      gru_loadA(feat, row0, smem, t);
      __syncthreads();
    }
    float (*accN)[4][4] = p ? accGh : accGi;
    const uint32_t aK = (uint32_t)(c * 128);  // k-chunk offset in A (64 cols * 2B)

    // passes 1,2: Ah*Bh, Al*Bh
    #pragma unroll
    for (int pass = 0; pass < 2; pass++) {
      uint32_t ab  = sb + (pass ? R_ALO : R_AHI) + a_lane + aK;
      uint32_t bbD = sb + bhBase[c] + bD_lane;
      uint32_t bbN = sb + bhBase[c] + bN_lane;
      #pragma unroll
      for (int ks = 0; ks < 4; ks++) {
        uint32_t a0[4], a1[4];
        ldsm4(a0, ab + ks*32);
        ldsm4(a1, ab + 16*GP + ks*32);
        #pragma unroll
        for (int np = 0; np < 4; np++) {
          uint32_t b4[4];
          ldsm4(b4, bbD + np*16*RBP + ks*32);
          mma16816(accD[0][np*2],   a0, b4);
          mma16816(accD[0][np*2+1], a0, b4+2);
          mma16816(accD[1][np*2],   a1, b4);
          mma16816(accD[1][np*2+1], a1, b4+2);
        }
        #pragma unroll
        for (int np = 0; np < 2; np++) {
          uint32_t b4[4];
          ldsm4(b4, bbN + np*16*RBP + ks*32);
          mma16816(accN[0][np*2],   a0, b4);
          mma16816(accN[0][np*2+1], a0, b4+2);
          mma16816(accN[1][np*2],   a1, b4);
          mma16816(accN[1][np*2+1], a1, b4+2);
        }
      }
    }
    // Bl(q) ready
    if (q < 3) { CP_WAIT(1); } else { CP_WAIT(0); }
    __syncthreads();
    // pass 3: Ah*Bl
    {
      uint32_t ab  = sb + R_AHI + a_lane + aK;
      uint32_t bbD = sb + R_BL + bD_lane;
      uint32_t bbN = sb + R_BL + bN_lane;
      #pragma unroll
      for (int ks = 0; ks < 4; ks++) {
        uint32_t a0[4], a1[4];
        ldsm4(a0, ab + ks*32);
        ldsm4(a1, ab + 16*GP + ks*32);
        #pragma unroll
        for (int np = 0; np < 4; np++) {
          uint32_t b4[4];
          ldsm4(b4, bbD + np*16*RBP + ks*32);
          mma16816(accD[0][np*2],   a0, b4);
          mma16816(accD[0][np*2+1], a0, b4+2);
          mma16816(accD[1][np*2],   a1, b4);
          mma16816(accD[1][np*2+1], a1, b4+2);
        }
        #pragma unroll
        for (int np = 0; np < 2; np++) {
          uint32_t b4[4];
          ldsm4(b4, bbN + np*16*RBP + ks*32);
          mma16816(accN[0][np*2],   a0, b4);
          mma16816(accN[0][np*2+1], a0, b4+2);
          mma16816(accN[1][np*2],   a1, b4);
          mma16816(accN[1][np*2+1], a1, b4+2);
        }
      }
    }
    __syncthreads();
    // tail prefetches: Bl(q+1), then Bh(q+2)
    if (q < 3) gru_issueB(bsrc_hi[q+1] + 24576, sb, R_BL, t);
    if (q < 2) gru_issueB(bsrc_hi[q+2], sb, bhBase[c], t);
  }

  // ---- stage accumulators to smem (overlays B buffers) ----
  __syncthreads();
  {
    const int r_lo = lane >> 2, c_off = (lane & 3)*2;
    float* base = (float*)(smem + R_STAG);
    // dense -> R/Z planes
    #pragma unroll
    for (int mt = 0; mt < 2; mt++) {
      #pragma unroll
      for (int nt = 0; nt < 8; nt++) {
        int C = g*64 + nt*8 + c_off;
        float* plane = base + (C >> 7)*64*132;
        int col = C & 127;
        int row = m0 + mt*16 + r_lo;
        *(float2*)(plane + row*132 + col)     = make_float2(accD[mt][nt][0], accD[mt][nt][1]);
        *(float2*)(plane + (row+8)*132 + col) = make_float2(accD[mt][nt][2], accD[mt][nt][3]);
      }
    }
    // gi / gh planes
    #pragma unroll
    for (int mt = 0; mt < 2; mt++) {
      #pragma unroll
      for (int nt = 0; nt < 4; nt++) {
        int col = g*32 + nt*8 + c_off;
        int row = m0 + mt*16 + r_lo;
        float* pGi = base + 2*64*132;
        float* pGh = base + 3*64*132;
        *(float2*)(pGi + row*132 + col)     = make_float2(accGi[mt][nt][0], accGi[mt][nt][1]);
        *(float2*)(pGi + (row+8)*132 + col) = make_float2(accGi[mt][nt][2], accGi[mt][nt][3]);
        *(float2*)(pGh + row*132 + col)     = make_float2(accGh[mt][nt][0], accGh[mt][nt][1]);
        *(float2*)(pGh + (row+8)*132 + col) = make_float2(accGh[mt][nt][2], accGh[mt][nt][3]);
      }
    }
  }
  __syncthreads();

  // ---- epilogue: combine gates, GRU nonlinearity, residual ----
  const float* pR  = (const float*)(smem + R_STAG);
  const float* pZ  = pR + 64*132;
  const float* pGi = pR + 2*64*132;
  const float* pGh = pR + 3*64*132;
  #pragma unroll
  for (int it = 0; it < 8; it++) {
    int idx = it*1024 + t*4;
    int row = idx >> 7, col = idx & 127;
    int so = row*132 + col;
    float4 rv = *(const float4*)(pR + so);
    float4 zv = *(const float4*)(pZ + so);
    float4 gi = *(const float4*)(pGi + so);
    float4 gh = *(const float4*)(pGh + so);
    float4 hv = *(const float4*)(feat + (size_t)(row0 + row)*HH + col);
    float rr[4] = {rv.x, rv.y, rv.z, rv.w};
    float zz[4] = {zv.x, zv.y, zv.z, zv.w};
    float gg[4] = {gi.x, gi.y, gi.z, gi.w};
    float hh2[4] = {gh.x, gh.y, gh.z, gh.w};
    float hx[4] = {hv.x, hv.y, hv.z, hv.w};
    float ox[4];
    #pragma unroll
    for (int e = 0; e < 4; e++) {
      int j = col + e;
      float r_ = rr[e] + __ldg(b_ih + j)       + __ldg(b_hh + j);
      float z_ = zz[e] + __ldg(b_ih + 128 + j) + __ldg(b_hh + 128 + j);
      float gi_ = gg[e]  + __ldg(b_ih + 256 + j);
      float gh_ = hh2[e] + __ldg(b_hh + 256 + j);
      float rs_ = 1.f / (1.f + __expf(-r_));
      float zs_ = 1.f / (1.f + __expf(-z_));
      float tx = gi_ + rs_ * gh_;
      float et = __expf(2.f * tx);
      float nn = 1.f - 2.f / (et + 1.f);
      float h = hx[e];
      ox[e] = h + nn + zs_ * (h - nn);
    }
    *(float4*)(out + (size_t)(row0 + row)*HH + col) = make_float4(ox[0], ox[1], ox[2], ox[3]);
  }
}

// ---------------------------------------------------------------------------
extern "C" void kernel_launch(void* const* d_in, const int* in_sizes, int n_in,
                              void* d_out, int out_size) {
  (void)in_sizes; (void)n_in; (void)out_size;
  const float* feat = (const float*)d_in[0];
  const float* W1   = (const float*)d_in[1];
  const float* b1   = (const float*)d_in[2];
  const float* W3   = (const float*)d_in[3];
  const float* b3   = (const float*)d_in[4];
  const float* Wih  = (const float*)d_in[5];
  const float* bih  = (const float*)d_in[6];
  const float* Whh  = (const float*)d_in[7];
  const float* bhh  = (const float*)d_in[8];
  float* out = (float*)d_out;

  float *st1, *st3, *rs;
  __nv_bfloat16 *w1i, *w3i;
  cudaGetSymbolAddress((void**)&st1, g_state1);
  cudaGetSymbolAddress((void**)&st3, g_state3);
  cudaGetSymbolAddress((void**)&rs,  g_rowsum);
  cudaGetSymbolAddress((void**)&w1i, g_W1img);
  cudaGetSymbolAddress((void**)&w3i, g_W3img);

  cudaFuncSetAttribute(gemm_s_mma, cudaFuncAttributeMaxDynamicSharedMemorySize, G_SMEM);
  cudaFuncSetAttribute(gru_mma,    cudaFuncAttributeMaxDynamicSharedMemorySize, R_SMEM);

  prep_kernel<<<2048, 256>>>(W1, W3, Wih, Whh);
  gemm_s_mma<<<dim3(BB/128, SS), 256, G_SMEM>>>(feat, nullptr, w1i, b1, st1);
  rowsum_kernel<<<(BB*32)/256, 256>>>(st1, rs);
  gemm_s_mma<<<dim3(BB/128, SS), 256, G_SMEM>>>(st1, rs, w3i, b3, st3);
  gru_mma<<<NROWS/64, 256, R_SMEM>>>(feat, st3, bih, bhh, out);
}